// round 15
// baseline (speedup 1.0000x reference)
#include <cuda_runtime.h>
#include <cuda_bf16.h>
#include <cstdint>

// Problem constants
#define D_EMBED 1024
#define N_HEAD  16
#define DH      64
#define LEN     1024
#define SEQ_S   3072
#define BATCH   2

// Scratch (device globals — NEVER passed as kernel args from host)
__device__ float g_Q  [BATCH * LEN   * D_EMBED];   // tf32 bits
__device__ float g_K  [BATCH * SEQ_S * D_EMBED];   // tf32 bits; reused attn_out fp32
__device__ float g_V  [BATCH * SEQ_S * D_EMBED];   // tf32 bits
__device__ float g_CTX[BATCH * LEN   * D_EMBED];   // tf32 bits
__device__ float g_rQin[BATCH * LEN   * D_EMBED];  // pre-rounded inputs
__device__ float g_rKV [BATCH * SEQ_S * D_EMBED];
__device__ float g_rW  [4 * D_EMBED * D_EMBED];    // Wq,Wk,Wv,Wout

// ---------------------------------------------------------------------------
// helpers (baseline sm_80+ PTX only)
// ---------------------------------------------------------------------------
__device__ __forceinline__ uint32_t s2u(const void* p) {
    return (uint32_t)__cvta_generic_to_shared(p);
}
__device__ __forceinline__ uint32_t f2tf(float f) {
    uint32_t r;
    asm("cvt.rna.tf32.f32 %0, %1;" : "=r"(r) : "f"(f));
    return r;
}
__device__ __forceinline__ void mma_tf32(float* d, uint32_t a0, uint32_t a1,
                                         uint32_t a2, uint32_t a3,
                                         uint32_t b0, uint32_t b1) {
    asm volatile("mma.sync.aligned.m16n8k8.row.col.f32.tf32.tf32.f32 "
                 "{%0,%1,%2,%3}, {%4,%5,%6,%7}, {%8,%9}, {%0,%1,%2,%3};"
                 : "+f"(d[0]), "+f"(d[1]), "+f"(d[2]), "+f"(d[3])
                 : "r"(a0), "r"(a1), "r"(a2), "r"(a3), "r"(b0), "r"(b1));
}
__device__ __forceinline__ void cp_async16(uint32_t dst, const void* src) {
    asm volatile("cp.async.cg.shared.global [%0], [%1], 16;"
                 :: "r"(dst), "l"(src) : "memory");
}
__device__ __forceinline__ void cp_commit() {
    asm volatile("cp.async.commit_group;" ::: "memory");
}
template <int N>
__device__ __forceinline__ void cp_wait() {
    asm volatile("cp.async.wait_group %0;" :: "n"(N) : "memory");
}

// ---------------------------------------------------------------------------
// pre-round kernels: fp32 -> tf32-rounded fp32 bits (dst chosen INSIDE kernel)
// dst_sel: 0 = g_rQin, 1 = g_rW   (+ dst_off4 in float4 units)
// ---------------------------------------------------------------------------
__global__ void __launch_bounds__(256) preround(const float* __restrict__ src,
                                                int n4, int dst_sel, int dst_off4)
{
    const int i = blockIdx.x * 256 + threadIdx.x;
    if (i >= n4) return;
    float* dst = (dst_sel == 0) ? g_rQin : g_rW;
    const uint4 v = ((const uint4*)src)[i];
    uint4 o;
    o.x = f2tf(__uint_as_float(v.x));
    o.y = f2tf(__uint_as_float(v.y));
    o.z = f2tf(__uint_as_float(v.z));
    o.w = f2tf(__uint_as_float(v.w));
    ((uint4*)dst)[(size_t)dst_off4 + i] = o;
}

__global__ void __launch_bounds__(256) preround_kv(const float* __restrict__ kv1,
                                                   const float* __restrict__ kv2)
{
    const int i = blockIdx.x * 256 + threadIdx.x;   // over 6144*256 float4s
    const int row = i >> 8;
    const int c4  = i & 255;
    const int b = row / SEQ_S;
    const int s = row % SEQ_S;
    const float* srow = (s < LEN)
        ? kv1 + ((size_t)b * LEN + s) * D_EMBED
        : kv2 + ((size_t)b * 2 * LEN + (s - LEN)) * D_EMBED;
    const uint4 v = ((const uint4*)srow)[c4];
    uint4 o;
    o.x = f2tf(__uint_as_float(v.x));
    o.y = f2tf(__uint_as_float(v.y));
    o.z = f2tf(__uint_as_float(v.z));
    o.w = f2tf(__uint_as_float(v.w));
    ((uint4*)(g_rKV + (size_t)row * D_EMBED))[c4] = o;
}

// ---------------------------------------------------------------------------
// tf32 tensor-core GEMM (cvt-free) — VERBATIM R11 (proven)
//   amode : 0 = g_rQin, 1 = g_rKV, 2 = g_CTX
//   woff  : W = g_rW + woff * 1024*1024
//   out_sel: 0 = g_Q, 1 = g_K, 2 = g_V, 3 = fused KV (bn<1024 -> g_K else g_V)
//   round_out: 1 -> write tf32-rounded bits, 0 -> exact fp32
// ---------------------------------------------------------------------------
#define GS 36                             // smem row stride in u32
#define G_TP_U32  (2 * 128 * GS)          // A+B pair per buffer (u32)
#define G_SMEM_BYTES (2 * G_TP_U32 * 4)   // 73728

__global__ void __launch_bounds__(256) gemm_tf32(
    const float* __restrict__ bias, int amode, int woff, int out_sel,
    int round_out)
{
    extern __shared__ uint32_t su[];
    const uint32_t smb = s2u(su);

    const int tid = threadIdx.x;
    const int wid = tid >> 5;
    const int lan = tid & 31;
    const int bm  = blockIdx.y * 128;
    const int bn  = blockIdx.x * 128;

    const float* A = (amode == 0) ? g_rQin : (amode == 1) ? g_rKV : g_CTX;
    const float* W = g_rW + (size_t)woff * D_EMBED * D_EMBED;
    float* C;
    int cbn;
    if (out_sel == 3) {
        C   = (bn < 1024) ? g_K : g_V;
        cbn = bn & 1023;
    } else {
        C   = (out_sel == 0) ? g_Q : (out_sel == 1) ? g_K : g_V;
        cbn = bn;
    }

    const int mw = wid & 3;
    const int nw = wid >> 2;
    const int g  = lan >> 2;
    const int tg = lan & 3;

    const int lr = tid >> 1;
    const int lc = (tid & 1) * 16;

    const float* arow = A + (size_t)(bm + lr) * D_EMBED;
    const float* brow = W + (size_t)(bn + lr) * D_EMBED;

    float acc[2][8][4];
    #pragma unroll
    for (int mt = 0; mt < 2; mt++)
        #pragma unroll
        for (int nt = 0; nt < 8; nt++)
            #pragma unroll
            for (int e = 0; e < 4; e++) acc[mt][nt][e] = 0.f;

    const int aBase = (mw * 32 + g) * GS + tg;
    const int bBase = (nw * 64 + g) * GS + tg;

    const uint32_t dA0 = smb + (uint32_t)(lr * GS + lc) * 4;
    const uint32_t dB0 = dA0 + 128 * GS * 4;

    auto issue_tile = [&](int buf, int it) {
        const int kg = it * 32;
        const uint32_t off = (uint32_t)buf * (G_TP_U32 * 4);
        #pragma unroll
        for (int j = 0; j < 4; j++) {
            cp_async16(dA0 + off + j * 16, arow + kg + lc + 4 * j);
            cp_async16(dB0 + off + j * 16, brow + kg + lc + 4 * j);
        }
        cp_commit();
    };

    issue_tile(0, 0);

    for (int it = 0; it < 32; it++) {
        cp_wait<0>();
        __syncthreads();
        if (it + 1 < 32) issue_tile((it + 1) & 1, it + 1);

        const uint32_t* sA = su + (it & 1) * G_TP_U32;
        const uint32_t* sB = sA + 128 * GS;

        #pragma unroll
        for (int ks = 0; ks < 4; ks++) {
            const int ko = ks * 8;
            uint32_t af[2][4];
            #pragma unroll
            for (int mt = 0; mt < 2; mt++) {
                const int ab = aBase + mt * 16 * GS + ko;
                af[mt][0] = sA[ab];
                af[mt][1] = sA[ab + 8 * GS];
                af[mt][2] = sA[ab + 4];
                af[mt][3] = sA[ab + 8 * GS + 4];
            }
            uint32_t bf[8][2];
            #pragma unroll
            for (int nt = 0; nt < 8; nt++) {
                const int bb = bBase + nt * 8 * GS + ko;
                bf[nt][0] = sB[bb];
                bf[nt][1] = sB[bb + 4];
            }
            #pragma unroll
            for (int mt = 0; mt < 2; mt++)
                #pragma unroll
                for (int nt = 0; nt < 8; nt++)
                    mma_tf32(acc[mt][nt], af[mt][0], af[mt][1], af[mt][2],
                             af[mt][3], bf[nt][0], bf[nt][1]);
        }
    }

    const int erow = g;
    const int ecol = tg * 2;
    #pragma unroll
    for (int mt = 0; mt < 2; mt++) {
        const int row = bm + mw * 32 + mt * 16 + erow;
        #pragma unroll
        for (int nt = 0; nt < 8; nt++) {
            const int col = nw * 64 + nt * 8 + ecol;
            const float c0 = __ldg(bias + bn + col), c1 = __ldg(bias + bn + col + 1);
            float r0 = acc[mt][nt][0] + c0, r1 = acc[mt][nt][1] + c1;
            float r2 = acc[mt][nt][2] + c0, r3 = acc[mt][nt][3] + c1;
            if (round_out) {
                r0 = __uint_as_float(f2tf(r0)); r1 = __uint_as_float(f2tf(r1));
                r2 = __uint_as_float(f2tf(r2)); r3 = __uint_as_float(f2tf(r3));
            }
            float2 lo, hi;
            lo.x = r0; lo.y = r1;
            hi.x = r2; hi.y = r3;
            *(float2*)(C + (size_t)row * 1024 + cbn + col)       = lo;
            *(float2*)(C + (size_t)(row + 8) * 1024 + cbn + col) = hi;
        }
    }
}

// ---------------------------------------------------------------------------
// Tensor-core flash attention — R10-proven 256-thread mt=1 body; ONE qt per
// block via qt_map so SM-paired blocks (bid, bid+148 -> x, x+4 mod 8) have
// qt summing to 7: 2 co-resident CTAs/SM (124 regs, 106KB smem each) with
// constant combined work (54 tile-units) -> balance + cross-CTA overlap.
// ---------------------------------------------------------------------------
#define QSTR 68
#define KSTR 68
#define VSTR 72
#define A_QP   0
#define A_K0   (128 * QSTR)                     // 8704
#define A_KSZ  (64 * KSTR)                      // 4352
#define A_V0   (A_K0 + 2 * A_KSZ)               // 17408
#define A_VSZ  (64 * VSTR)                      // 4608
#define A_U32  (A_V0 + 2 * A_VSZ)               // 26624
#define ATC_SMEM_BYTES (A_U32 * 4)              // 106496

__global__ void __launch_bounds__(256) attn_tc()
{
    extern __shared__ uint32_t su[];
    const uint32_t smb = s2u(su);
    uint32_t* QP = su + A_QP;

    const int tid = threadIdx.x;
    const int wid = tid >> 5;
    const int lan = tid & 31;
    const int g   = lan >> 2;
    const int t   = lan & 3;
    const int qt_map[8] = {7, 5, 3, 1, 0, 2, 4, 6};
    const int qt  = qt_map[blockIdx.x];
    const int b   = blockIdx.y >> 4;
    const int h   = blockIdx.y & 15;
    const int q0  = qt * 128;
    const int mrow = wid * 16;

    // ---- load Q tile (128 x 64, already tf32 bits) ----
    {
        const float* Qbase = g_Q + ((size_t)(b * LEN + q0)) * D_EMBED + h * DH;
        #pragma unroll
        for (int rep = 0; rep < 8; rep++) {
            const int li  = tid + rep * 256;
            const int row = li >> 4;
            const int c4  = (li & 15) << 2;
            uint4 v = *(const uint4*)(Qbase + (size_t)row * D_EMBED + c4);
            *(uint4*)(QP + row * QSTR + c4) = v;
        }
    }
    __syncthreads();

    // ---- hoist Q fragments to registers, then QP becomes P ----
    uint32_t qf[8][4];
    #pragma unroll
    for (int ks = 0; ks < 8; ks++) {
        const int ko = ks * 8;
        qf[ks][0] = QP[(mrow + g) * QSTR + ko + t];
        qf[ks][1] = QP[(mrow + g + 8) * QSTR + ko + t];
        qf[ks][2] = QP[(mrow + g) * QSTR + ko + t + 4];
        qf[ks][3] = QP[(mrow + g + 8) * QSTR + ko + t + 4];
    }
    __syncwarp();

    float ctx[8][4];
    #pragma unroll
    for (int dt = 0; dt < 8; dt++)
        #pragma unroll
        for (int e = 0; e < 4; e++) ctx[dt][e] = 0.f;
    float m0 = -1e30f, m1 = -1e30f, l0 = 0.f, l1 = 0.f;

    const int qrow0 = q0 + mrow + g;
    const int qrow1 = qrow0 + 8;

    const int per = 2 * qt + 2;              // key tiles per segment
    const int T   = 3 * per;

    const int krow = tid >> 2;
    const int kcol = (tid & 3) * 16;
    const float* KH = g_K + ((size_t)b * SEQ_S) * D_EMBED + h * DH;
    const float* VH = g_V + ((size_t)b * SEQ_S) * D_EMBED + h * DH;

    auto issue_kv = [&](int buf, int ti) {
        const int seg = ti / per;
        const int kt  = ti - seg * per;
        const size_t rbase = (size_t)(seg * LEN + kt * 64 + krow) * D_EMBED + kcol;
        const uint32_t dk = smb + (A_K0 + buf * A_KSZ + krow * KSTR + kcol) * 4;
        const uint32_t dv = smb + (A_V0 + buf * A_VSZ + krow * VSTR + kcol) * 4;
        #pragma unroll
        for (int j = 0; j < 4; j++) {
            cp_async16(dk + j * 16, KH + rbase + 4 * j);
            cp_async16(dv + j * 16, VH + rbase + 4 * j);
        }
        cp_commit();
    };

    issue_kv(0, 0);

    for (int ti = 0; ti < T; ti++) {
        cp_wait<0>();
        __syncthreads();
        if (ti + 1 < T) issue_kv((ti + 1) & 1, ti + 1);

        const int seg = ti / per;
        const int s0  = (ti - seg * per) * 64;
        const uint32_t* Ks = su + A_K0 + (ti & 1) * A_KSZ;
        const uint32_t* Vs = su + A_V0 + (ti & 1) * A_VSZ;

        // ---- S = Q K^T ----
        float sf[8][4];
        #pragma unroll
        for (int nt = 0; nt < 8; nt++)
            #pragma unroll
            for (int e = 0; e < 4; e++) sf[nt][e] = 0.f;

        #pragma unroll
        for (int ks = 0; ks < 8; ks++) {
            const int ko = ks * 8;
            #pragma unroll
            for (int nt = 0; nt < 8; nt++) {
                const int kr = (nt * 8 + g) * KSTR + ko + t;
                mma_tf32(sf[nt], qf[ks][0], qf[ks][1], qf[ks][2], qf[ks][3],
                         Ks[kr], Ks[kr + 4]);
            }
        }

        // ---- scale + causal mask + row max ----
        float rmx0 = -1e30f, rmx1 = -1e30f;
        #pragma unroll
        for (int nt = 0; nt < 8; nt++) {
            const int c0 = s0 + nt * 8 + 2 * t;
            const int c1 = c0 + 1;
            float v0 = sf[nt][0] * 0.125f; if (c0 > qrow0) v0 = -1e30f;
            float v1 = sf[nt][1] * 0.125f; if (c1 > qrow0) v1 = -1e30f;
            float v2 = sf[nt][2] * 0.125f; if (c0 > qrow1) v2 = -1e30f;
            float v3 = sf[nt][3] * 0.125f; if (c1 > qrow1) v3 = -1e30f;
            sf[nt][0] = v0; sf[nt][1] = v1; sf[nt][2] = v2; sf[nt][3] = v3;
            rmx0 = fmaxf(rmx0, fmaxf(v0, v1));
            rmx1 = fmaxf(rmx1, fmaxf(v2, v3));
        }
        rmx0 = fmaxf(rmx0, __shfl_xor_sync(0xFFFFFFFFu, rmx0, 1));
        rmx0 = fmaxf(rmx0, __shfl_xor_sync(0xFFFFFFFFu, rmx0, 2));
        rmx1 = fmaxf(rmx1, __shfl_xor_sync(0xFFFFFFFFu, rmx1, 1));
        rmx1 = fmaxf(rmx1, __shfl_xor_sync(0xFFFFFFFFu, rmx1, 2));

        const float nm0 = fmaxf(m0, rmx0);
        const float nm1 = fmaxf(m1, rmx1);
        const float al0 = __expf(m0 - nm0);
        const float al1 = __expf(m1 - nm1);

        // ---- exp + row sum + stage P (tf32) ----
        float rs0 = 0.f, rs1 = 0.f;
        #pragma unroll
        for (int nt = 0; nt < 8; nt++) {
            const float p0 = __expf(sf[nt][0] - nm0);
            const float p1 = __expf(sf[nt][1] - nm0);
            const float p2 = __expf(sf[nt][2] - nm1);
            const float p3 = __expf(sf[nt][3] - nm1);
            rs0 += p0 + p1;
            rs1 += p2 + p3;
            const int cc = nt * 8 + 2 * t;
            uint2 w0, w1;
            w0.x = f2tf(p0); w0.y = f2tf(p1);
            w1.x = f2tf(p2); w1.y = f2tf(p3);
            *(uint2*)(QP + (mrow + g) * QSTR + cc)     = w0;
            *(uint2*)(QP + (mrow + g + 8) * QSTR + cc) = w1;
        }
        rs0 += __shfl_xor_sync(0xFFFFFFFFu, rs0, 1);
        rs0 += __shfl_xor_sync(0xFFFFFFFFu, rs0, 2);
        rs1 += __shfl_xor_sync(0xFFFFFFFFu, rs1, 1);
        rs1 += __shfl_xor_sync(0xFFFFFFFFu, rs1, 2);

        l0 = l0 * al0 + rs0; m0 = nm0;
        l1 = l1 * al1 + rs1; m1 = nm1;

        #pragma unroll
        for (int dt = 0; dt < 8; dt++) {
            ctx[dt][0] *= al0; ctx[dt][1] *= al0;
            ctx[dt][2] *= al1; ctx[dt][3] *= al1;
        }
        __syncwarp();

        // ---- ctx += P V ----
        #pragma unroll
        for (int ks = 0; ks < 8; ks++) {
            const int ko = ks * 8;
            const uint32_t a0 = QP[(mrow + g) * QSTR + ko + t];
            const uint32_t a1 = QP[(mrow + g + 8) * QSTR + ko + t];
            const uint32_t a2 = QP[(mrow + g) * QSTR + ko + t + 4];
            const uint32_t a3 = QP[(mrow + g + 8) * QSTR + ko + t + 4];
            #pragma unroll
            for (int dt = 0; dt < 8; dt++) {
                mma_tf32(ctx[dt], a0, a1, a2, a3,
                         Vs[(ko + t) * VSTR + dt * 8 + g],
                         Vs[(ko + t + 4) * VSTR + dt * 8 + g]);
            }
        }
        __syncwarp();
    }

    // ---- epilogue: write tf32-rounded ctx ----
    const float inv0 = 1.f / l0;
    const float inv1 = 1.f / l1;
    float* o0 = g_CTX + ((size_t)(b * LEN + q0 + mrow + g)) * D_EMBED + h * DH;
    float* o1 = o0 + 8 * D_EMBED;
    #pragma unroll
    for (int dt = 0; dt < 8; dt++) {
        const int cc = dt * 8 + 2 * t;
        float2 w0, w1;
        w0.x = __uint_as_float(f2tf(ctx[dt][0] * inv0));
        w0.y = __uint_as_float(f2tf(ctx[dt][1] * inv0));
        w1.x = __uint_as_float(f2tf(ctx[dt][2] * inv1));
        w1.y = __uint_as_float(f2tf(ctx[dt][3] * inv1));
        *(float2*)(o0 + cc) = w0;
        *(float2*)(o1 + cc) = w1;
    }
}

// ---------------------------------------------------------------------------
// Residual + LayerNorm + mask epilogue (attn_out read from g_K internally)
// ---------------------------------------------------------------------------
__global__ void __launch_bounds__(256) ln_mask_kernel(
    const float* __restrict__ hq, const float* __restrict__ lng,
    const float* __restrict__ lnb, const float* __restrict__ mask,
    float* __restrict__ out)
{
    __shared__ float red[32];
    const int row = blockIdx.x;
    const int tid = threadIdx.x;

    const float4 a = *(const float4*)(hq  + (size_t)row * D_EMBED + tid * 4);
    const float4 c = *(const float4*)(g_K + (size_t)row * D_EMBED + tid * 4);
    const float x0 = a.x + c.x, x1 = a.y + c.y, x2 = a.z + c.z, x3 = a.w + c.w;

    float s  = x0 + x1 + x2 + x3;
    float ss = x0 * x0 + x1 * x1 + x2 * x2 + x3 * x3;
    #pragma unroll
    for (int o = 16; o > 0; o >>= 1) {
        s  += __shfl_xor_sync(0xFFFFFFFFu, s,  o);
        ss += __shfl_xor_sync(0xFFFFFFFFu, ss, o);
    }
    const int w = tid >> 5;
    if ((tid & 31) == 0) { red[w] = s; red[w + 8] = ss; }
    __syncthreads();
    if (tid < 32) {
        float s2  = (tid < 8) ? red[tid]     : 0.f;
        float ss2 = (tid < 8) ? red[tid + 8] : 0.f;
        #pragma unroll
        for (int o = 4; o > 0; o >>= 1) {
            s2  += __shfl_xor_sync(0xFFFFFFFFu, s2,  o);
            ss2 += __shfl_xor_sync(0xFFFFFFFFu, ss2, o);
        }
        if (tid == 0) { red[16] = s2; red[17] = ss2; }
    }
    __syncthreads();

    const float mu   = red[16] * (1.f / 1024.f);
    const float var  = red[17] * (1.f / 1024.f) - mu * mu;
    const float rstd = rsqrtf(var + 1e-5f);
    const float mk   = mask[row];

    const float4 gg = *(const float4*)(lng + tid * 4);
    const float4 bb = *(const float4*)(lnb + tid * 4);
    float4 o;
    o.x = ((x0 - mu) * rstd * gg.x + bb.x) * mk;
    o.y = ((x1 - mu) * rstd * gg.y + bb.y) * mk;
    o.z = ((x2 - mu) * rstd * gg.z + bb.z) * mk;
    o.w = ((x3 - mu) * rstd * gg.w + bb.w) * mk;
    *(float4*)(out + (size_t)row * D_EMBED + tid * 4) = o;
}

// ---------------------------------------------------------------------------
extern "C" void kernel_launch(void* const* d_in, const int* in_sizes, int n_in,
                              void* d_out, int out_size)
{
    const float* h_q   = (const float*)d_in[0];
    const float* h_kv1 = (const float*)d_in[1];
    const float* h_kv2 = (const float*)d_in[2];
    const float* mask  = (const float*)d_in[3];
    const float* w_in  = (const float*)d_in[4];
    const float* b_in  = (const float*)d_in[5];
    const float* w_out = (const float*)d_in[6];
    const float* b_out = (const float*)d_in[7];
    const float* ln_g  = (const float*)d_in[8];
    const float* ln_b  = (const float*)d_in[9];
    float* out = (float*)d_out;

    cudaFuncSetAttribute(gemm_tf32,
                         cudaFuncAttributeMaxDynamicSharedMemorySize,
                         G_SMEM_BYTES);
    cudaFuncSetAttribute(attn_tc,
                         cudaFuncAttributeMaxDynamicSharedMemorySize,
                         ATC_SMEM_BYTES);

    // pre-round inputs/weights to tf32 bits (dst selected inside kernels)
    preround   <<<2048, 256>>>(h_q,  2048 * 256, 0, 0);
    preround_kv<<<6144, 256>>>(h_kv1, h_kv2);
    preround   <<<3072, 256>>>(w_in,  3072 * 256, 1, 0);
    preround   <<<1024, 256>>>(w_out, 1024 * 256, 1, 3072 * 256);

    // Q = h_q @ Wq^T + bq  (tf32-rounded out)
    gemm_tf32<<<dim3(8, 16), 256, G_SMEM_BYTES>>>(b_in, 0, 0, 0, 1);
    // fused K+V projection: N=2048 (Wk|Wv contiguous), A tiles loaded once
    gemm_tf32<<<dim3(16, 48), 256, G_SMEM_BYTES>>>(b_in + 1024, 1, 1, 3, 1);
    // attention -> g_CTX: 256 blocks, one qt each, SM-pairs balanced by qt_map,
    // 2 CTAs/SM co-resident
    attn_tc<<<dim3(8, BATCH * N_HEAD), 256, ATC_SMEM_BYTES>>>();
    // attn_out = ctx @ out_w^T + out_b  (exact fp32, into g_K)
    gemm_tf32<<<dim3(8, 16), 256, G_SMEM_BYTES>>>(b_out, 2, 3, 1, 0);
    // residual + LN + mask
    ln_mask_kernel<<<BATCH * LEN, 256>>>(h_q, ln_g, ln_b, mask, out);
}

// round 17
// speedup vs baseline: 1.1273x; 1.1273x over previous
#include <cuda_runtime.h>
#include <cuda_bf16.h>
#include <cstdint>

// Problem constants
#define D_EMBED 1024
#define N_HEAD  16
#define DH      64
#define LEN     1024
#define SEQ_S   3072
#define BATCH   2

// Scratch (device globals — NEVER passed as kernel args from host)
__device__ float g_Q  [BATCH * LEN   * D_EMBED];   // tf32 bits
__device__ float g_K  [BATCH * SEQ_S * D_EMBED];   // tf32 bits; reused attn_out fp32
__device__ float g_V  [BATCH * SEQ_S * D_EMBED];   // tf32 bits
__device__ float g_CTX[BATCH * LEN   * D_EMBED];   // tf32 bits
__device__ float g_rQin[BATCH * LEN   * D_EMBED];  // pre-rounded inputs
__device__ float g_rKV [BATCH * SEQ_S * D_EMBED];
__device__ float g_rW  [4 * D_EMBED * D_EMBED];    // Wq,Wk,Wv,Wout

// ---------------------------------------------------------------------------
// helpers (baseline sm_80+ PTX only)
// ---------------------------------------------------------------------------
__device__ __forceinline__ uint32_t s2u(const void* p) {
    return (uint32_t)__cvta_generic_to_shared(p);
}
__device__ __forceinline__ uint32_t f2tf(float f) {
    uint32_t r;
    asm("cvt.rna.tf32.f32 %0, %1;" : "=r"(r) : "f"(f));
    return r;
}
__device__ __forceinline__ void mma_tf32(float* d, uint32_t a0, uint32_t a1,
                                         uint32_t a2, uint32_t a3,
                                         uint32_t b0, uint32_t b1) {
    asm volatile("mma.sync.aligned.m16n8k8.row.col.f32.tf32.tf32.f32 "
                 "{%0,%1,%2,%3}, {%4,%5,%6,%7}, {%8,%9}, {%0,%1,%2,%3};"
                 : "+f"(d[0]), "+f"(d[1]), "+f"(d[2]), "+f"(d[3])
                 : "r"(a0), "r"(a1), "r"(a2), "r"(a3), "r"(b0), "r"(b1));
}
__device__ __forceinline__ void cp_async16(uint32_t dst, const void* src) {
    asm volatile("cp.async.cg.shared.global [%0], [%1], 16;"
                 :: "r"(dst), "l"(src) : "memory");
}
__device__ __forceinline__ void cp_commit() {
    asm volatile("cp.async.commit_group;" ::: "memory");
}
template <int N>
__device__ __forceinline__ void cp_wait() {
    asm volatile("cp.async.wait_group %0;" :: "n"(N) : "memory");
}

// ---------------------------------------------------------------------------
// pre-round kernels: fp32 -> tf32-rounded fp32 bits (dst chosen INSIDE kernel)
// dst_sel: 0 = g_rQin, 1 = g_rW   (+ dst_off4 in float4 units)
// ---------------------------------------------------------------------------
__global__ void __launch_bounds__(256) preround(const float* __restrict__ src,
                                                int n4, int dst_sel, int dst_off4)
{
    const int i = blockIdx.x * 256 + threadIdx.x;
    if (i >= n4) return;
    float* dst = (dst_sel == 0) ? g_rQin : g_rW;
    const uint4 v = ((const uint4*)src)[i];
    uint4 o;
    o.x = f2tf(__uint_as_float(v.x));
    o.y = f2tf(__uint_as_float(v.y));
    o.z = f2tf(__uint_as_float(v.z));
    o.w = f2tf(__uint_as_float(v.w));
    ((uint4*)dst)[(size_t)dst_off4 + i] = o;
}

__global__ void __launch_bounds__(256) preround_kv(const float* __restrict__ kv1,
                                                   const float* __restrict__ kv2)
{
    const int i = blockIdx.x * 256 + threadIdx.x;   // over 6144*256 float4s
    const int row = i >> 8;
    const int c4  = i & 255;
    const int b = row / SEQ_S;
    const int s = row % SEQ_S;
    const float* srow = (s < LEN)
        ? kv1 + ((size_t)b * LEN + s) * D_EMBED
        : kv2 + ((size_t)b * 2 * LEN + (s - LEN)) * D_EMBED;
    const uint4 v = ((const uint4*)srow)[c4];
    uint4 o;
    o.x = f2tf(__uint_as_float(v.x));
    o.y = f2tf(__uint_as_float(v.y));
    o.z = f2tf(__uint_as_float(v.z));
    o.w = f2tf(__uint_as_float(v.w));
    ((uint4*)(g_rKV + (size_t)row * D_EMBED))[c4] = o;
}

// ---------------------------------------------------------------------------
// tf32 tensor-core GEMM (cvt-free): C[m,n] = sum_k A[m,k]*W[n,k] + bias[n]
//   amode : 0 = g_rQin, 1 = g_rKV, 2 = g_CTX
//   woff  : W = g_rW + woff * 1024*1024
//   out_sel: 0 = g_Q, 1 = g_K, 2 = g_V, 3 = fused KV (bn<1024 -> g_K else g_V)
//   round_out: 1 -> write tf32-rounded bits, 0 -> exact fp32
// 128x128 tile, BK=32, cp.async 3-stage pipeline (2 groups in flight).
// ---------------------------------------------------------------------------
#define GS 36                             // smem row stride in u32
#define G_TP_U32  (2 * 128 * GS)          // A+B pair per buffer (u32)
#define G_SMEM_BYTES (3 * G_TP_U32 * 4)   // 110592 (3 buffers)

__global__ void __launch_bounds__(256) gemm_tf32(
    const float* __restrict__ bias, int amode, int woff, int out_sel,
    int round_out)
{
    extern __shared__ uint32_t su[];
    const uint32_t smb = s2u(su);

    const int tid = threadIdx.x;
    const int wid = tid >> 5;
    const int lan = tid & 31;
    const int bm  = blockIdx.y * 128;
    const int bn  = blockIdx.x * 128;

    const float* A = (amode == 0) ? g_rQin : (amode == 1) ? g_rKV : g_CTX;
    const float* W = g_rW + (size_t)woff * D_EMBED * D_EMBED;
    float* C;
    int cbn;
    if (out_sel == 3) {
        C   = (bn < 1024) ? g_K : g_V;
        cbn = bn & 1023;
    } else {
        C   = (out_sel == 0) ? g_Q : (out_sel == 1) ? g_K : g_V;
        cbn = bn;
    }

    const int mw = wid & 3;
    const int nw = wid >> 2;
    const int g  = lan >> 2;
    const int tg = lan & 3;

    const int lr = tid >> 1;
    const int lc = (tid & 1) * 16;

    const float* arow = A + (size_t)(bm + lr) * D_EMBED;
    const float* brow = W + (size_t)(bn + lr) * D_EMBED;

    float acc[2][8][4];
    #pragma unroll
    for (int mt = 0; mt < 2; mt++)
        #pragma unroll
        for (int nt = 0; nt < 8; nt++)
            #pragma unroll
            for (int e = 0; e < 4; e++) acc[mt][nt][e] = 0.f;

    const int aBase = (mw * 32 + g) * GS + tg;
    const int bBase = (nw * 64 + g) * GS + tg;

    const uint32_t dA0 = smb + (uint32_t)(lr * GS + lc) * 4;
    const uint32_t dB0 = dA0 + 128 * GS * 4;

    auto issue_tile = [&](int buf, int it) {
        const int kg = it * 32;
        const uint32_t off = (uint32_t)buf * (G_TP_U32 * 4);
        #pragma unroll
        for (int j = 0; j < 4; j++) {
            cp_async16(dA0 + off + j * 16, arow + kg + lc + 4 * j);
            cp_async16(dB0 + off + j * 16, brow + kg + lc + 4 * j);
        }
        cp_commit();
    };

    issue_tile(0, 0);
    issue_tile(1, 1);

    for (int it = 0; it < 32; it++) {
        if (it == 31) cp_wait<0>();       // last group is the one we need
        else          cp_wait<1>();       // group 'it' done; 'it+1' may fly
        __syncthreads();
        if (it + 2 < 32) issue_tile((it + 2) % 3, it + 2);

        const uint32_t* sA = su + (it % 3) * G_TP_U32;
        const uint32_t* sB = sA + 128 * GS;

        #pragma unroll
        for (int ks = 0; ks < 4; ks++) {
            const int ko = ks * 8;
            uint32_t af[2][4];
            #pragma unroll
            for (int mt = 0; mt < 2; mt++) {
                const int ab = aBase + mt * 16 * GS + ko;
                af[mt][0] = sA[ab];
                af[mt][1] = sA[ab + 8 * GS];
                af[mt][2] = sA[ab + 4];
                af[mt][3] = sA[ab + 8 * GS + 4];
            }
            uint32_t bf[8][2];
            #pragma unroll
            for (int nt = 0; nt < 8; nt++) {
                const int bb = bBase + nt * 8 * GS + ko;
                bf[nt][0] = sB[bb];
                bf[nt][1] = sB[bb + 4];
            }
            #pragma unroll
            for (int mt = 0; mt < 2; mt++)
                #pragma unroll
                for (int nt = 0; nt < 8; nt++)
                    mma_tf32(acc[mt][nt], af[mt][0], af[mt][1], af[mt][2],
                             af[mt][3], bf[nt][0], bf[nt][1]);
        }
    }

    const int erow = g;
    const int ecol = tg * 2;
    #pragma unroll
    for (int mt = 0; mt < 2; mt++) {
        const int row = bm + mw * 32 + mt * 16 + erow;
        #pragma unroll
        for (int nt = 0; nt < 8; nt++) {
            const int col = nw * 64 + nt * 8 + ecol;
            const float c0 = __ldg(bias + bn + col), c1 = __ldg(bias + bn + col + 1);
            float r0 = acc[mt][nt][0] + c0, r1 = acc[mt][nt][1] + c1;
            float r2 = acc[mt][nt][2] + c0, r3 = acc[mt][nt][3] + c1;
            if (round_out) {
                r0 = __uint_as_float(f2tf(r0)); r1 = __uint_as_float(f2tf(r1));
                r2 = __uint_as_float(f2tf(r2)); r3 = __uint_as_float(f2tf(r3));
            }
            float2 lo, hi;
            lo.x = r0; lo.y = r1;
            hi.x = r2; hi.y = r3;
            *(float2*)(C + (size_t)row * 1024 + cbn + col)       = lo;
            *(float2*)(C + (size_t)(row + 8) * 1024 + cbn + col) = hi;
        }
    }
}

// ---------------------------------------------------------------------------
// Tensor-core flash attention — VERBATIM R11 (proven 579us config):
// paired-qt persistent blocks, grid (4, 32), 256 threads, 1 CTA/SM,
// block bx handles qt = 7-bx then qt = bx (54 tile-units each).
// ---------------------------------------------------------------------------
#define QSTR 68
#define KSTR 68
#define VSTR 72
#define A_QP   0
#define A_K0   (128 * QSTR)                     // 8704
#define A_KSZ  (64 * KSTR)                      // 4352
#define A_V0   (A_K0 + 2 * A_KSZ)               // 17408
#define A_VSZ  (64 * VSTR)                      // 4608
#define A_U32  (A_V0 + 2 * A_VSZ)               // 26624
#define ATC_SMEM_BYTES (A_U32 * 4)              // 106496

__global__ void __launch_bounds__(256) attn_tc()
{
    extern __shared__ uint32_t su[];
    const uint32_t smb = s2u(su);
    uint32_t* QP = su + A_QP;

    const int tid = threadIdx.x;
    const int wid = tid >> 5;
    const int lan = tid & 31;
    const int g   = lan >> 2;
    const int t   = lan & 3;
    const int bx  = (int)blockIdx.x;         // 0..3
    const int b   = blockIdx.y >> 4;
    const int h   = blockIdx.y & 15;
    const int mrow = wid * 16;

    const int krow = tid >> 2;
    const int kcol = (tid & 3) * 16;
    const float* KH = g_K + ((size_t)b * SEQ_S) * D_EMBED + h * DH;
    const float* VH = g_V + ((size_t)b * SEQ_S) * D_EMBED + h * DH;

    #pragma unroll
    for (int pi = 0; pi < 2; pi++) {
        const int qt = pi ? bx : (7 - bx);   // big tile first, then small
        const int q0 = qt * 128;

        __syncthreads();
        {
            const float* Qbase = g_Q + ((size_t)(b * LEN + q0)) * D_EMBED + h * DH;
            #pragma unroll
            for (int rep = 0; rep < 8; rep++) {
                const int li  = tid + rep * 256;
                const int row = li >> 4;
                const int c4  = (li & 15) << 2;
                uint4 v = *(const uint4*)(Qbase + (size_t)row * D_EMBED + c4);
                *(uint4*)(QP + row * QSTR + c4) = v;
            }
        }
        __syncthreads();

        uint32_t qf[8][4];
        #pragma unroll
        for (int ks = 0; ks < 8; ks++) {
            const int ko = ks * 8;
            qf[ks][0] = QP[(mrow + g) * QSTR + ko + t];
            qf[ks][1] = QP[(mrow + g + 8) * QSTR + ko + t];
            qf[ks][2] = QP[(mrow + g) * QSTR + ko + t + 4];
            qf[ks][3] = QP[(mrow + g + 8) * QSTR + ko + t + 4];
        }
        __syncwarp();

        float ctx[8][4];
        #pragma unroll
        for (int dt = 0; dt < 8; dt++)
            #pragma unroll
            for (int e = 0; e < 4; e++) ctx[dt][e] = 0.f;
        float m0 = -1e30f, m1 = -1e30f, l0 = 0.f, l1 = 0.f;

        const int qrow0 = q0 + mrow + g;
        const int qrow1 = qrow0 + 8;

        const int per = 2 * qt + 2;          // key tiles per segment
        const int T   = 3 * per;

        auto issue_kv = [&](int buf, int ti) {
            const int seg = ti / per;
            const int kt  = ti - seg * per;
            const size_t rbase = (size_t)(seg * LEN + kt * 64 + krow) * D_EMBED + kcol;
            const uint32_t dk = smb + (A_K0 + buf * A_KSZ + krow * KSTR + kcol) * 4;
            const uint32_t dv = smb + (A_V0 + buf * A_VSZ + krow * VSTR + kcol) * 4;
            #pragma unroll
            for (int j = 0; j < 4; j++) {
                cp_async16(dk + j * 16, KH + rbase + 4 * j);
                cp_async16(dv + j * 16, VH + rbase + 4 * j);
            }
            cp_commit();
        };

        issue_kv(0, 0);

        for (int ti = 0; ti < T; ti++) {
            cp_wait<0>();
            __syncthreads();
            if (ti + 1 < T) issue_kv((ti + 1) & 1, ti + 1);

            const int seg = ti / per;
            const int s0  = (ti - seg * per) * 64;
            const uint32_t* Ks = su + A_K0 + (ti & 1) * A_KSZ;
            const uint32_t* Vs = su + A_V0 + (ti & 1) * A_VSZ;

            // ---- S = Q K^T ----
            float sf[8][4];
            #pragma unroll
            for (int nt = 0; nt < 8; nt++)
                #pragma unroll
                for (int e = 0; e < 4; e++) sf[nt][e] = 0.f;

            #pragma unroll
            for (int ks = 0; ks < 8; ks++) {
                const int ko = ks * 8;
                #pragma unroll
                for (int nt = 0; nt < 8; nt++) {
                    const int kr = (nt * 8 + g) * KSTR + ko + t;
                    mma_tf32(sf[nt], qf[ks][0], qf[ks][1], qf[ks][2], qf[ks][3],
                             Ks[kr], Ks[kr + 4]);
                }
            }

            // ---- scale + causal mask + row max ----
            float rmx0 = -1e30f, rmx1 = -1e30f;
            #pragma unroll
            for (int nt = 0; nt < 8; nt++) {
                const int c0 = s0 + nt * 8 + 2 * t;
                const int c1 = c0 + 1;
                float v0 = sf[nt][0] * 0.125f; if (c0 > qrow0) v0 = -1e30f;
                float v1 = sf[nt][1] * 0.125f; if (c1 > qrow0) v1 = -1e30f;
                float v2 = sf[nt][2] * 0.125f; if (c0 > qrow1) v2 = -1e30f;
                float v3 = sf[nt][3] * 0.125f; if (c1 > qrow1) v3 = -1e30f;
                sf[nt][0] = v0; sf[nt][1] = v1; sf[nt][2] = v2; sf[nt][3] = v3;
                rmx0 = fmaxf(rmx0, fmaxf(v0, v1));
                rmx1 = fmaxf(rmx1, fmaxf(v2, v3));
            }
            rmx0 = fmaxf(rmx0, __shfl_xor_sync(0xFFFFFFFFu, rmx0, 1));
            rmx0 = fmaxf(rmx0, __shfl_xor_sync(0xFFFFFFFFu, rmx0, 2));
            rmx1 = fmaxf(rmx1, __shfl_xor_sync(0xFFFFFFFFu, rmx1, 1));
            rmx1 = fmaxf(rmx1, __shfl_xor_sync(0xFFFFFFFFu, rmx1, 2));

            const float nm0 = fmaxf(m0, rmx0);
            const float nm1 = fmaxf(m1, rmx1);
            const float al0 = __expf(m0 - nm0);
            const float al1 = __expf(m1 - nm1);

            // ---- exp + row sum + stage P (tf32) ----
            float rs0 = 0.f, rs1 = 0.f;
            #pragma unroll
            for (int nt = 0; nt < 8; nt++) {
                const float p0 = __expf(sf[nt][0] - nm0);
                const float p1 = __expf(sf[nt][1] - nm0);
                const float p2 = __expf(sf[nt][2] - nm1);
                const float p3 = __expf(sf[nt][3] - nm1);
                rs0 += p0 + p1;
                rs1 += p2 + p3;
                const int cc = nt * 8 + 2 * t;
                uint2 w0, w1;
                w0.x = f2tf(p0); w0.y = f2tf(p1);
                w1.x = f2tf(p2); w1.y = f2tf(p3);
                *(uint2*)(QP + (mrow + g) * QSTR + cc)     = w0;
                *(uint2*)(QP + (mrow + g + 8) * QSTR + cc) = w1;
            }
            rs0 += __shfl_xor_sync(0xFFFFFFFFu, rs0, 1);
            rs0 += __shfl_xor_sync(0xFFFFFFFFu, rs0, 2);
            rs1 += __shfl_xor_sync(0xFFFFFFFFu, rs1, 1);
            rs1 += __shfl_xor_sync(0xFFFFFFFFu, rs1, 2);

            l0 = l0 * al0 + rs0; m0 = nm0;
            l1 = l1 * al1 + rs1; m1 = nm1;

            #pragma unroll
            for (int dt = 0; dt < 8; dt++) {
                ctx[dt][0] *= al0; ctx[dt][1] *= al0;
                ctx[dt][2] *= al1; ctx[dt][3] *= al1;
            }
            __syncwarp();

            // ---- ctx += P V ----
            #pragma unroll
            for (int ks = 0; ks < 8; ks++) {
                const int ko = ks * 8;
                const uint32_t a0 = QP[(mrow + g) * QSTR + ko + t];
                const uint32_t a1 = QP[(mrow + g + 8) * QSTR + ko + t];
                const uint32_t a2 = QP[(mrow + g) * QSTR + ko + t + 4];
                const uint32_t a3 = QP[(mrow + g + 8) * QSTR + ko + t + 4];
                #pragma unroll
                for (int dt = 0; dt < 8; dt++) {
                    mma_tf32(ctx[dt], a0, a1, a2, a3,
                             Vs[(ko + t) * VSTR + dt * 8 + g],
                             Vs[(ko + t + 4) * VSTR + dt * 8 + g]);
                }
            }
            __syncwarp();
        }

        // ---- epilogue: write tf32-rounded ctx ----
        const float inv0 = 1.f / l0;
        const float inv1 = 1.f / l1;
        float* o0 = g_CTX + ((size_t)(b * LEN + q0 + mrow + g)) * D_EMBED + h * DH;
        float* o1 = o0 + 8 * D_EMBED;
        #pragma unroll
        for (int dt = 0; dt < 8; dt++) {
            const int cc = dt * 8 + 2 * t;
            float2 w0, w1;
            w0.x = __uint_as_float(f2tf(ctx[dt][0] * inv0));
            w0.y = __uint_as_float(f2tf(ctx[dt][1] * inv0));
            w1.x = __uint_as_float(f2tf(ctx[dt][2] * inv1));
            w1.y = __uint_as_float(f2tf(ctx[dt][3] * inv1));
            *(float2*)(o0 + cc) = w0;
            *(float2*)(o1 + cc) = w1;
        }
    }
}

// ---------------------------------------------------------------------------
// Residual + LayerNorm + mask epilogue (attn_out read from g_K internally)
// ---------------------------------------------------------------------------
__global__ void __launch_bounds__(256) ln_mask_kernel(
    const float* __restrict__ hq, const float* __restrict__ lng,
    const float* __restrict__ lnb, const float* __restrict__ mask,
    float* __restrict__ out)
{
    __shared__ float red[32];
    const int row = blockIdx.x;
    const int tid = threadIdx.x;

    const float4 a = *(const float4*)(hq  + (size_t)row * D_EMBED + tid * 4);
    const float4 c = *(const float4*)(g_K + (size_t)row * D_EMBED + tid * 4);
    const float x0 = a.x + c.x, x1 = a.y + c.y, x2 = a.z + c.z, x3 = a.w + c.w;

    float s  = x0 + x1 + x2 + x3;
    float ss = x0 * x0 + x1 * x1 + x2 * x2 + x3 * x3;
    #pragma unroll
    for (int o = 16; o > 0; o >>= 1) {
        s  += __shfl_xor_sync(0xFFFFFFFFu, s,  o);
        ss += __shfl_xor_sync(0xFFFFFFFFu, ss, o);
    }
    const int w = tid >> 5;
    if ((tid & 31) == 0) { red[w] = s; red[w + 8] = ss; }
    __syncthreads();
    if (tid < 32) {
        float s2  = (tid < 8) ? red[tid]     : 0.f;
        float ss2 = (tid < 8) ? red[tid + 8] : 0.f;
        #pragma unroll
        for (int o = 4; o > 0; o >>= 1) {
            s2  += __shfl_xor_sync(0xFFFFFFFFu, s2,  o);
            ss2 += __shfl_xor_sync(0xFFFFFFFFu, ss2, o);
        }
        if (tid == 0) { red[16] = s2; red[17] = ss2; }
    }
    __syncthreads();

    const float mu   = red[16] * (1.f / 1024.f);
    const float var  = red[17] * (1.f / 1024.f) - mu * mu;
    const float rstd = rsqrtf(var + 1e-5f);
    const float mk   = mask[row];

    const float4 gg = *(const float4*)(lng + tid * 4);
    const float4 bb = *(const float4*)(lnb + tid * 4);
    float4 o;
    o.x = ((x0 - mu) * rstd * gg.x + bb.x) * mk;
    o.y = ((x1 - mu) * rstd * gg.y + bb.y) * mk;
    o.z = ((x2 - mu) * rstd * gg.z + bb.z) * mk;
    o.w = ((x3 - mu) * rstd * gg.w + bb.w) * mk;
    *(float4*)(out + (size_t)row * D_EMBED + tid * 4) = o;
}

// ---------------------------------------------------------------------------
extern "C" void kernel_launch(void* const* d_in, const int* in_sizes, int n_in,
                              void* d_out, int out_size)
{
    const float* h_q   = (const float*)d_in[0];
    const float* h_kv1 = (const float*)d_in[1];
    const float* h_kv2 = (const float*)d_in[2];
    const float* mask  = (const float*)d_in[3];
    const float* w_in  = (const float*)d_in[4];
    const float* b_in  = (const float*)d_in[5];
    const float* w_out = (const float*)d_in[6];
    const float* b_out = (const float*)d_in[7];
    const float* ln_g  = (const float*)d_in[8];
    const float* ln_b  = (const float*)d_in[9];
    float* out = (float*)d_out;

    cudaFuncSetAttribute(gemm_tf32,
                         cudaFuncAttributeMaxDynamicSharedMemorySize,
                         G_SMEM_BYTES);
    cudaFuncSetAttribute(attn_tc,
                         cudaFuncAttributeMaxDynamicSharedMemorySize,
                         ATC_SMEM_BYTES);

    // pre-round inputs/weights to tf32 bits (dst selected inside kernels)
    preround   <<<2048, 256>>>(h_q,  2048 * 256, 0, 0);
    preround_kv<<<6144, 256>>>(h_kv1, h_kv2);
    preround   <<<3072, 256>>>(w_in,  3072 * 256, 1, 0);
    preround   <<<1024, 256>>>(w_out, 1024 * 256, 1, 3072 * 256);

    // Q = h_q @ Wq^T + bq  (tf32-rounded out)
    gemm_tf32<<<dim3(8, 16), 256, G_SMEM_BYTES>>>(b_in, 0, 0, 0, 1);
    // fused K+V projection: N=2048 (Wk|Wv contiguous), A tiles loaded once
    gemm_tf32<<<dim3(16, 48), 256, G_SMEM_BYTES>>>(b_in + 1024, 1, 1, 3, 1);
    // attention -> g_CTX (tf32-rounded), paired-qt balanced grid (R11)
    attn_tc<<<dim3(4, BATCH * N_HEAD), 256, ATC_SMEM_BYTES>>>();
    // attn_out = ctx @ out_w^T + out_b  (exact fp32, into g_K)
    gemm_tf32<<<dim3(8, 16), 256, G_SMEM_BYTES>>>(b_out, 2, 3, 1, 0);
    // residual + LN + mask
    ln_mask_kernel<<<BATCH * LEN, 256>>>(h_q, ln_g, ln_b, mask, out);
}